// round 8
// baseline (speedup 1.0000x reference)
#include <cuda_runtime.h>

// ---------------- scratch (device globals; no allocation allowed) ----------------
__device__ float g_A1[221184];    // layer1 eff weights: [(o*9+j)][kk(96)][n(16)]
__device__ float g_A2[688128];    // layer2 eff weights: [j][kk(384)][col(256)] col=o*8+n
__device__ float g_t1[4718592];   // [b][c16][j9][n8]
__device__ float g_t2[3670016];   // [b][c32][j7][l4]
__device__ float g_t3[1310720];   // [b][o*5+j]
__device__ float g_red[224];      // sum1[16] ssq1[16] sum2[32] ssq2[32] sum3[64] ssq3[64]
__device__ float g_bn1[32];       // [scale16][shift16]
__device__ float g_bn2[64];       // [scale32][shift32]
__device__ float g_bn3[128];      // [scale64][shift64]

typedef unsigned long long ull;

__device__ __forceinline__ void fma2(ull& d, ull a, ull b) {
    asm("fma.rn.f32x2 %0, %1, %2, %0;" : "+l"(d) : "l"(a), "l"(b));
}
__device__ __forceinline__ ull dup2(float v) {
    ull r;
    asm("mov.b64 %0, {%1, %1};" : "=l"(r) : "f"(v));
    return r;
}
__device__ __forceinline__ float warp_sum(float v) {
    #pragma unroll
    for (int o = 16; o; o >>= 1) v += __shfl_down_sync(0xffffffffu, v, o);
    return v;
}

__global__ void k_zero() {
    if (threadIdx.x < 224) g_red[threadIdx.x] = 0.f;
}

// Build layer1 effective weights. A1[(o,j)][kk=c*16+p][n]
__global__ void k_prep1(const float* __restrict__ w1) {
    int id = blockIdx.x * blockDim.x + threadIdx.x;
    if (id >= 221184) return;
    int n  = id & 15;
    int kk = (id >> 4) % 96;
    int oj = id / 1536;
    int o = oj / 9, j = oj % 9;
    int c = kk >> 4, p = kk & 15;
    int h = 1 << j;
    int d = p - n;
    float v = 0.f;
    if (d >= -3 * h && d <= 3 * h) {
        float t = (float)d / (float)h;
        #pragma unroll
        for (int mm = 0; mm < 7; mm++) {
            float hat = 1.f - fabsf(t - (float)(mm - 3));
            if (hat > 0.f) v += w1[(o * 6 + c) * 7 + mm] * hat;
        }
        v /= (float)h;
    }
    g_A1[id] = v;
}

// Build layer2 effective weights. A2[j][kk=(c*3+r)*8+p][col=o*8+n]
__global__ void k_prep2(const float* __restrict__ w2) {
    int id = blockIdx.x * blockDim.x + threadIdx.x;
    if (id >= 688128) return;
    int col = id & 255;
    int kk  = (id >> 8) % 384;
    int j   = id / 98304;
    int o = col >> 3, n = col & 7;
    int p = kk & 7;
    int cr = kk >> 3;               // c*3+r
    int h = 1 << j;
    int d = p - n;
    float v = 0.f;
    if (d >= -h && d <= h) {
        float t = (float)d / (float)h;
        #pragma unroll
        for (int mm = 0; mm < 3; mm++) {
            float hat = 1.f - fabsf(t - (float)(mm - 1));
            if (hat > 0.f) v += w2[(o * 48 + cr) * 3 + mm] * hat;
        }
        v /= (float)h;
    }
    g_A2[id] = v;
}

// ---------------------------------------------------------------------------
// Layer1: C[4096 x 2304] = X[4096 x 96] * A1[96 x 2304], fused pool+relu+stats.
// Block 128 rows x 64 cols, 256 threads. Thread tile: 8 consecutive rows
// (8*rg..8*rg+7) x 4 cols (4*cg..). Both operands via LDS.128:
// per k: 2 a-LDS.128 + 2 w-LDS.128 + 16 FMA2.
// smem: aT[48][132] + wD[48][132] = 50688 B (strides 16B-aligned). 4 blk/SM.
// ---------------------------------------------------------------------------
__global__ void __launch_bounds__(256, 4) k_layer1(const float* __restrict__ x) {
    extern __shared__ float sm[];
    float* aT = sm;               // [48][132]  aT[k][row]
    float* wD = sm + 6336;        // [48][132]  dup col-pairs: wD[k][2*col]
    const int t = threadIdx.x;
    const int b0  = blockIdx.x * 128;
    const int oj0 = blockIdx.y * 4;

    const int rg = t & 15, cg = t >> 4;   // rows 8rg..8rg+7, cols 4cg..4cg+3
    ull acc[4][4];                        // [row-pair q][col c]
    #pragma unroll
    for (int q = 0; q < 4; q++)
        #pragma unroll
        for (int c = 0; c < 4; c++) acc[q][c] = 0ull;

    for (int kt = 0; kt < 2; kt++) {
        __syncthreads();
        // acts transposed: aT[kk][r]
        for (int i = t; i < 6144; i += 256) {
            int r = i / 48, kk = i - r * 48;
            aT[kk * 132 + r] = x[(b0 + r) * 96 + kt * 48 + kk];
        }
        // weights duplicated: wD[kk][2*col] = {w,w}, col < 64
        for (int i = t; i < 3072; i += 256) {
            int kk = i >> 6, col = i & 63;
            int g = col >> 4, n = col & 15;
            float v = g_A1[(oj0 + g) * 1536 + (kt * 48 + kk) * 16 + n];
            *reinterpret_cast<float2*>(wD + kk * 132 + 2 * col) = make_float2(v, v);
        }
        __syncthreads();

        const float* pa = aT + 8 * rg;
        const float* pw = wD + 8 * cg;
        #pragma unroll 4
        for (int k = 0; k < 48; k++) {
            ulonglong2 a0 = *reinterpret_cast<const ulonglong2*>(pa + k * 132);
            ulonglong2 a1 = *reinterpret_cast<const ulonglong2*>(pa + k * 132 + 4);
            ulonglong2 w0 = *reinterpret_cast<const ulonglong2*>(pw + k * 132);
            ulonglong2 w1 = *reinterpret_cast<const ulonglong2*>(pw + k * 132 + 4);
            ull av[4] = {a0.x, a0.y, a1.x, a1.y};
            ull wv[4] = {w0.x, w0.y, w1.x, w1.y};
            #pragma unroll
            for (int q = 0; q < 4; q++)
                #pragma unroll
                for (int c = 0; c < 4; c++) fma2(acc[q][c], av[q], wv[c]);
        }
    }
    __syncthreads();

    // pre[128][65] reuses smem
    float* pre = sm;
    #pragma unroll
    for (int q = 0; q < 4; q++)
        #pragma unroll
        for (int c = 0; c < 4; c++) {
            float2 v = *reinterpret_cast<float2*>(&acc[q][c]);
            int r0 = 8 * rg + 2 * q;
            pre[r0 * 65 + cg * 4 + c]       = v.x;
            pre[(r0 + 1) * 65 + cg * 4 + c] = v.y;
        }
    __syncthreads();

    // Pool(4,s2,p1)+relu+stats. thread = (row = t&127, half = t>>7) -> 2 oj groups
    const int row = t & 127, half = t >> 7;
    const float* pr = pre + row * 65;
    long base = (long)(b0 + row) * 1152;
    #pragma unroll
    for (int gg = 0; gg < 2; gg++) {
        int g = half * 2 + gg;
        int oj = oj0 + g;
        int o = oj / 9, jj = oj - o * 9;
        float* dst = g_t1 + base + o * 72 + jj * 8;
        float s = 0.f, ss = 0.f;
        float m8[8];
        #pragma unroll
        for (int k = 0; k < 8; k++) {
            int lo = (2 * k - 1 < 0) ? 0 : 2 * k - 1;
            int hi = (2 * k + 2 > 15) ? 15 : 2 * k + 2;
            float m = pr[g * 16 + lo];
            for (int nn = lo + 1; nn <= hi; nn++) m = fmaxf(m, pr[g * 16 + nn]);
            m = fmaxf(m, 0.f);
            m8[k] = m;
            s += m; ss += m * m;
        }
        *reinterpret_cast<float4*>(dst)     = make_float4(m8[0], m8[1], m8[2], m8[3]);
        *reinterpret_cast<float4*>(dst + 4) = make_float4(m8[4], m8[5], m8[6], m8[7]);
        float sA = warp_sum(s), ssA = warp_sum(ss);
        if ((t & 31) == 0) {
            atomicAdd(&g_red[o], sA);
            atomicAdd(&g_red[16 + o], ssA);
        }
    }
}

__global__ void k_bnparam(const float* __restrict__ g, const float* __restrict__ b, int layer) {
    int c = threadIdx.x;
    int nch, off; float count; float* bn;
    if (layer == 1)      { nch = 16; off = 0;  count = 294912.f; bn = g_bn1; }
    else if (layer == 2) { nch = 32; off = 32; count = 114688.f; bn = g_bn2; }
    else                 { nch = 64; off = 96; count = 20480.f;  bn = g_bn3; }
    if (c >= nch) return;
    float sum = g_red[off + c], ssq = g_red[off + nch + c];
    float mean = sum / count;
    float var = ssq / count - mean * mean;
    float sc = g[c] * rsqrtf(var + 2e-5f);
    bn[c] = sc;
    bn[nch + c] = b[c] - mean * sc;
}

// ---------------------------------------------------------------------------
// Layer2: per j: C[4096 x 256] = acts[4096 x 384] * A2[j], BN1 folded,
// fused pool+relu+stats. Block 128 rows x 64 cols (8 o2), 256 threads.
// Thread tile 8 consecutive rows x 4 cols, LDS.128 operands. K in 6 tiles of 64.
// smem: aT[64][132] + wD[64][132] = 67584 B. 3 blk/SM.
// ---------------------------------------------------------------------------
__global__ void __launch_bounds__(256, 3) k_layer2() {
    extern __shared__ float sm[];
    __shared__ float bnS[32];
    float* aT = sm;               // [64][132]
    float* wD = sm + 8448;        // [64][132]
    const int t = threadIdx.x;
    const int b0 = blockIdx.x * 128;
    const int cb = blockIdx.y;    // col block: o2 channels cb*8..+7
    const int j  = blockIdx.z;

    if (t < 32) bnS[t] = g_bn1[t];

    const int rg = t & 15, cg = t >> 4;
    ull acc[4][4];
    #pragma unroll
    for (int q = 0; q < 4; q++)
        #pragma unroll
        for (int c = 0; c < 4; c++) acc[q][c] = 0ull;

    const float* wbase = g_A2 + j * 98304 + cb * 64;

    for (int kt = 0; kt < 6; kt++) {
        __syncthreads();
        // acts tile transposed (BN1 folded): aT[kk][r]
        for (int i = t; i < 8192; i += 256) {
            int r = i >> 6, kk = i & 63;
            int k = kt * 64 + kk;
            int c = k / 24, rem = k - c * 24;
            float v = g_t1[(long)(b0 + r) * 1152 + c * 72 + j * 8 + rem];
            aT[kk * 132 + r] = v * bnS[c] + bnS[16 + c];
        }
        // weight tile duplicated: wD[kk][2*col], col < 64
        for (int i = t; i < 4096; i += 256) {
            int kk = i >> 6, col = i & 63;
            float v = wbase[(kt * 64 + kk) * 256 + col];
            *reinterpret_cast<float2*>(wD + kk * 132 + 2 * col) = make_float2(v, v);
        }
        __syncthreads();

        const float* pa = aT + 8 * rg;
        const float* pw = wD + 8 * cg;
        #pragma unroll 4
        for (int k = 0; k < 64; k++) {
            ulonglong2 a0 = *reinterpret_cast<const ulonglong2*>(pa + k * 132);
            ulonglong2 a1 = *reinterpret_cast<const ulonglong2*>(pa + k * 132 + 4);
            ulonglong2 w0 = *reinterpret_cast<const ulonglong2*>(pw + k * 132);
            ulonglong2 w1 = *reinterpret_cast<const ulonglong2*>(pw + k * 132 + 4);
            ull av[4] = {a0.x, a0.y, a1.x, a1.y};
            ull wv[4] = {w0.x, w0.y, w1.x, w1.y};
            #pragma unroll
            for (int q = 0; q < 4; q++)
                #pragma unroll
                for (int c = 0; c < 4; c++) fma2(acc[q][c], av[q], wv[c]);
        }
    }
    __syncthreads();

    float* pre = sm;              // [128][65]
    #pragma unroll
    for (int q = 0; q < 4; q++)
        #pragma unroll
        for (int c = 0; c < 4; c++) {
            float2 v = *reinterpret_cast<float2*>(&acc[q][c]);
            int r0 = 8 * rg + 2 * q;
            pre[r0 * 65 + cg * 4 + c]       = v.x;
            pre[(r0 + 1) * 65 + cg * 4 + c] = v.y;
        }
    __syncthreads();

    // Pool(4,s2,p1)+relu+stats. thread = (row, half) -> 4 o2 channels
    const int row = t & 127, half = t >> 7;
    const float* pr = pre + row * 65;
    long tbase = (long)(b0 + row) * 896 + j * 4;
    #pragma unroll
    for (int ol = 0; ol < 4; ol++) {
        int lc = half * 4 + ol;             // local col group within block (0..7)
        int o2g = cb * 8 + lc;              // global o2 channel
        float s = 0.f, ss = 0.f;
        float m4[4];
        #pragma unroll
        for (int k = 0; k < 4; k++) {
            int lo = (2 * k - 1 < 0) ? 0 : 2 * k - 1;
            int hi = (2 * k + 2 > 7) ? 7 : 2 * k + 2;
            float m = pr[lc * 8 + lo];
            for (int nn = lo + 1; nn <= hi; nn++) m = fmaxf(m, pr[lc * 8 + nn]);
            m = fmaxf(m, 0.f);
            m4[k] = m;
            s += m; ss += m * m;
        }
        *reinterpret_cast<float4*>(g_t2 + tbase + o2g * 28) =
            make_float4(m4[0], m4[1], m4[2], m4[3]);
        float sA = warp_sum(s), ssA = warp_sum(ss);
        if ((t & 31) == 0) {
            atomicAdd(&g_red[32 + o2g], sA);
            atomicAdd(&g_red[64 + o2g], ssA);
        }
    }
}

// ---------------------------------------------------------------------------
// Layer3: per batch-tile of 16 rows. acts transposed [idx 896][18] (BN2 folded)
// so row-pairs are natural LDS.64 (warp-uniform broadcast). Weights [kidx][o3].
// Row-pair f32x2 accumulation halves fma-pipe time vs scalar.
// smem floats: actsT 896*18=16128 | ws 96*64=6144 => 89088 B. 2 blocks/SM.
// ---------------------------------------------------------------------------
__global__ void __launch_bounds__(256, 2) k_layer3(const float* __restrict__ w3) {
    extern __shared__ float sm[];
    float* actsT = sm;             // [896][18]
    float* ws    = sm + 16128;     // [96][64]
    __shared__ float st[128];
    const int t = threadIdx.x;
    const int b0 = blockIdx.x * 16;

    for (int i = t; i < 14336; i += 256) {
        int r = i / 896, idx = i - r * 896;
        int c = idx / 28;
        actsT[idx * 18 + r] = g_t2[(long)b0 * 896 + i] * g_bn2[c] + g_bn2[32 + c];
    }
    for (int i = t; i < 6144; i += 256) {
        int kidx = i >> 6, o = i & 63;
        int c = kidx / 3, rr = kidx - c * 3;
        ws[i] = w3[(o * 32 + c) * 3 + rr];  // w3[...,0]: last dim is 1
    }
    if (t < 128) st[t] = 0.f;
    __syncthreads();

    const int o3 = t & 63, rpg = t >> 6;   // rpg warp-uniform
    const ull* a64 = reinterpret_cast<const ull*>(actsT);  // stride 9 per idx
    const float invj[5] = {1.f, 0.5f, 0.25f, 0.125f, 0.0625f};
    float s = 0.f, ssq = 0.f;

    #pragma unroll
    for (int hf = 0; hf < 2; hf++) {
        const int rp = rpg + 4 * hf;       // row-pair: rows 2rp, 2rp+1
        ull accp[15];
        #pragma unroll
        for (int i = 0; i < 15; i++) accp[i] = 0ull;

        for (int c = 0; c < 32; c++) {
            ull av[21];                    // [m 0..6][l 0..2] row-pairs (broadcast)
            #pragma unroll
            for (int m = 0; m < 7; m++)
                #pragma unroll
                for (int l = 0; l < 3; l++)
                    av[m * 3 + l] = a64[(c * 28 + m * 4 + l) * 9 + rp];
            ull w0 = dup2(ws[(c * 3 + 0) * 64 + o3]);
            ull w1 = dup2(ws[(c * 3 + 1) * 64 + o3]);
            ull w2 = dup2(ws[(c * 3 + 2) * 64 + o3]);
            #pragma unroll
            for (int jj = 0; jj < 5; jj++)
                #pragma unroll
                for (int l = 0; l < 3; l++) {
                    fma2(accp[jj * 3 + l], w0, av[(jj + 0) * 3 + l]);
                    fma2(accp[jj * 3 + l], w1, av[(jj + 1) * 3 + l]);
                    fma2(accp[jj * 3 + l], w2, av[(jj + 2) * 3 + l]);
                }
        }
        // pool over l + relu + scale, both rows of the pair
        #pragma unroll
        for (int jj = 0; jj < 5; jj++) {
            float2 v0 = *reinterpret_cast<float2*>(&accp[jj * 3 + 0]);
            float2 v1 = *reinterpret_cast<float2*>(&accp[jj * 3 + 1]);
            float2 v2 = *reinterpret_cast<float2*>(&accp[jj * 3 + 2]);
            float mx = fmaxf(fmaxf(v0.x, v1.x), v2.x) * invj[jj];
            float my = fmaxf(fmaxf(v0.y, v1.y), v2.y) * invj[jj];
            mx = fmaxf(mx, 0.f); my = fmaxf(my, 0.f);
            g_t3[(b0 + 2 * rp) * 320 + o3 * 5 + jj]     = mx;
            g_t3[(b0 + 2 * rp + 1) * 320 + o3 * 5 + jj] = my;
            s += mx + my; ssq += mx * mx + my * my;
        }
    }
    atomicAdd(&st[o3], s);
    atomicAdd(&st[64 + o3], ssq);
    __syncthreads();
    if (t < 64) { atomicAdd(&g_red[96 + t], st[t]); atomicAdd(&g_red[160 + t], st[64 + t]); }
}

// BN3 + 3-layer MLP. One thread per sample; t3 tiles staged through smem.
__global__ void __launch_bounds__(128) k_fc(const float* __restrict__ fw1, const float* __restrict__ fb1,
                                            const float* __restrict__ fw2, const float* __restrict__ fb2,
                                            const float* __restrict__ fw3, const float* __restrict__ fb3,
                                            float* __restrict__ out) {
    __shared__ float w1s[5120];            // transposed [k][o]
    __shared__ float vt[128 * 33];
    __shared__ float w2s[256];
    __shared__ float w3s[272];
    __shared__ float b1s[16], b2s[16], b3s[17];
    int t = threadIdx.x;
    int bbase = blockIdx.x * 128;
    for (int i = t; i < 5120; i += 128) { int o = i / 320, k = i % 320; w1s[k * 16 + o] = fw1[i]; }
    for (int i = t; i < 256; i += 128) w2s[i] = fw2[i];
    for (int i = t; i < 272; i += 128) w3s[i] = fw3[i];
    if (t < 16) { b1s[t] = fb1[t]; b2s[t] = fb2[t]; }
    if (t < 17) b3s[t] = fb3[t];
    __syncthreads();

    float h1[16];
    #pragma unroll
    for (int o = 0; o < 16; o++) h1[o] = b1s[o];

    for (int i0 = 0; i0 < 320; i0 += 32) {
        __syncthreads();
        for (int idx = t; idx < 4096; idx += 128) {
            int r = idx >> 5, c2 = idx & 31;
            int i = i0 + c2, ch = i / 5;
            vt[r * 33 + c2] = g_t3[(bbase + r) * 320 + i] * g_bn3[ch] + g_bn3[64 + ch];
        }
        __syncthreads();
        #pragma unroll 4
        for (int c2 = 0; c2 < 32; c2++) {
            float v = vt[t * 33 + c2];
            const float* wr = &w1s[(i0 + c2) * 16];
            #pragma unroll
            for (int o = 0; o < 16; o++) h1[o] += v * wr[o];
        }
    }
    float h2[16];
    #pragma unroll
    for (int o = 0; o < 16; o++) {
        float a = b2s[o];
        #pragma unroll
        for (int k = 0; k < 16; k++) a += h1[k] * w2s[o * 16 + k];
        h2[o] = a;
    }
    int b = bbase + t;
    #pragma unroll
    for (int o = 0; o < 17; o++) {
        float a = b3s[o];
        #pragma unroll
        for (int k = 0; k < 16; k++) a += h2[k] * w3s[o * 16 + k];
        out[b * 17 + o] = a;
    }
}

extern "C" void kernel_launch(void* const* d_in, const int* in_sizes, int n_in,
                              void* d_out, int out_size) {
    const float* x   = (const float*)d_in[0];
    const float* w1  = (const float*)d_in[1];
    const float* w2  = (const float*)d_in[2];
    const float* w3  = (const float*)d_in[3];
    const float* g1  = (const float*)d_in[4];
    const float* b1  = (const float*)d_in[5];
    const float* g2  = (const float*)d_in[6];
    const float* b2  = (const float*)d_in[7];
    const float* g3  = (const float*)d_in[8];
    const float* b3  = (const float*)d_in[9];
    const float* fw1 = (const float*)d_in[10];
    const float* fb1 = (const float*)d_in[11];
    const float* fw2 = (const float*)d_in[12];
    const float* fb2 = (const float*)d_in[13];
    const float* fw3 = (const float*)d_in[14];
    const float* fb3 = (const float*)d_in[15];
    float* out = (float*)d_out;

    cudaFuncSetAttribute(k_layer1, cudaFuncAttributeMaxDynamicSharedMemorySize, 50688);
    cudaFuncSetAttribute(k_layer2, cudaFuncAttributeMaxDynamicSharedMemorySize, 67584);
    cudaFuncSetAttribute(k_layer3, cudaFuncAttributeMaxDynamicSharedMemorySize, 89088);

    k_zero<<<1, 256>>>();
    k_prep1<<<(221184 + 255) / 256, 256>>>(w1);
    k_prep2<<<(688128 + 255) / 256, 256>>>(w2);
    k_layer1<<<dim3(32, 36), 256, 50688>>>(x);
    k_bnparam<<<1, 64>>>(g1, b1, 1);
    k_layer2<<<dim3(32, 4, 7), 256, 67584>>>();
    k_bnparam<<<1, 64>>>(g2, b2, 2);
    k_layer3<<<256, 256, 89088>>>(w3);
    k_bnparam<<<1, 64>>>(g3, b3, 3);
    k_fc<<<32, 128>>>(fw1, fb1, fw2, fb2, fw3, fb3, out);
}

// round 9
// speedup vs baseline: 1.3303x; 1.3303x over previous
#include <cuda_runtime.h>

// ---------------- scratch (device globals; no allocation allowed) ----------------
__device__ float g_A1[221184];    // layer1 eff weights: [(o*9+j)][kk(96)][n(16)]
__device__ float g_A2[688128];    // layer2 eff weights: [j][kk(384)][col(256)] col=o*8+n
__device__ float g_t1[4718592];   // [b][c16][j9][n8]
__device__ float g_t2[3670016];   // [b][c32][j7][l4]
__device__ float g_t3[1310720];   // [b][o*5+j]
__device__ float g_red[224];      // sum1[16] ssq1[16] sum2[32] ssq2[32] sum3[64] ssq3[64]
__device__ float g_bn1[32];       // [scale16][shift16]
__device__ float g_bn2[64];       // [scale32][shift32]
__device__ float g_bn3[128];      // [scale64][shift64]

typedef unsigned long long ull;

__device__ __forceinline__ void fma2(ull& d, ull a, ull b) {
    asm("fma.rn.f32x2 %0, %1, %2, %0;" : "+l"(d) : "l"(a), "l"(b));
}
__device__ __forceinline__ ull dup2(float v) {
    ull r;
    asm("mov.b64 %0, {%1, %1};" : "=l"(r) : "f"(v));
    return r;
}
__device__ __forceinline__ float warp_sum(float v) {
    #pragma unroll
    for (int o = 16; o; o >>= 1) v += __shfl_down_sync(0xffffffffu, v, o);
    return v;
}

__global__ void k_zero() {
    if (threadIdx.x < 224) g_red[threadIdx.x] = 0.f;
}

// Build layer1 effective weights. A1[(o,j)][kk=c*16+p][n]
__global__ void k_prep1(const float* __restrict__ w1) {
    int id = blockIdx.x * blockDim.x + threadIdx.x;
    if (id >= 221184) return;
    int n  = id & 15;
    int kk = (id >> 4) % 96;
    int oj = id / 1536;
    int o = oj / 9, j = oj % 9;
    int c = kk >> 4, p = kk & 15;
    int h = 1 << j;
    int d = p - n;
    float v = 0.f;
    if (d >= -3 * h && d <= 3 * h) {
        float t = (float)d / (float)h;
        #pragma unroll
        for (int mm = 0; mm < 7; mm++) {
            float hat = 1.f - fabsf(t - (float)(mm - 3));
            if (hat > 0.f) v += w1[(o * 6 + c) * 7 + mm] * hat;
        }
        v /= (float)h;
    }
    g_A1[id] = v;
}

// Build layer2 effective weights. A2[j][kk=(c*3+r)*8+p][col=o*8+n]
__global__ void k_prep2(const float* __restrict__ w2) {
    int id = blockIdx.x * blockDim.x + threadIdx.x;
    if (id >= 688128) return;
    int col = id & 255;
    int kk  = (id >> 8) % 384;
    int j   = id / 98304;
    int o = col >> 3, n = col & 7;
    int p = kk & 7;
    int cr = kk >> 3;               // c*3+r
    int h = 1 << j;
    int d = p - n;
    float v = 0.f;
    if (d >= -h && d <= h) {
        float t = (float)d / (float)h;
        #pragma unroll
        for (int mm = 0; mm < 3; mm++) {
            float hat = 1.f - fabsf(t - (float)(mm - 1));
            if (hat > 0.f) v += w2[(o * 48 + cr) * 3 + mm] * hat;
        }
        v /= (float)h;
    }
    g_A2[id] = v;
}

// ---------------------------------------------------------------------------
// Layer1: C[4096 x 2304] = X[4096 x 96] * A1[96 x 2304], fused pool+relu+stats.
// Block 128 rows x 128 cols (8 oj groups), 256 threads. Col-pair FMA2:
// thread = rows {rg+16i} x cols {8cg+2p+e}. Per k: 8 LDS.32(a) + 8 mov-dup
// + 4 LDS.64(w natural col-pairs) + 32 FMA2  => 1 B/MAC crossbar.
// smem: aT[96][129] + wT[96][130] = 99456 B, single K tile. 2 blk/SM.
// ---------------------------------------------------------------------------
__global__ void __launch_bounds__(256, 2) k_layer1(const float* __restrict__ x) {
    extern __shared__ float sm[];
    float* aT = sm;               // [96][129]  aT[k][row]
    float* wT = sm + 12384;       // [96][130]  wT[k][col]
    const int t = threadIdx.x;
    const int b0  = blockIdx.x * 128;
    const int oj0 = blockIdx.y * 8;
    const int rg = t & 15, cg = t >> 4;   // rows rg+16i, col-pairs 4cg+p

    // stage X (conflict-free: lanes walk kk, bank = kk mod 32)
    for (int i = t; i < 12288; i += 256) {
        int r = i / 96, kk = i - r * 96;
        aT[kk * 129 + r] = x[(b0 + r) * 96 + kk];
    }
    // stage W natural (no dup)
    for (int i = t; i < 12288; i += 256) {
        int kk = i >> 7, col = i & 127;
        int g = col >> 4, n = col & 15;
        wT[kk * 130 + col] = g_A1[(oj0 + g) * 1536 + kk * 16 + n];
    }
    __syncthreads();

    ull acc[8][4];
    #pragma unroll
    for (int i = 0; i < 8; i++)
        #pragma unroll
        for (int p = 0; p < 4; p++) acc[i][p] = 0ull;

    const float* pa = aT + rg;
    const float* pw = wT + 8 * cg;
    #pragma unroll 2
    for (int k = 0; k < 96; k++) {
        ull wv[4];
        #pragma unroll
        for (int p = 0; p < 4; p++)
            wv[p] = *reinterpret_cast<const ull*>(pw + k * 130 + 2 * p);
        ull ad[8];
        #pragma unroll
        for (int i = 0; i < 8; i++) ad[i] = dup2(pa[k * 129 + 16 * i]);
        #pragma unroll
        for (int i = 0; i < 8; i++)
            #pragma unroll
            for (int p = 0; p < 4; p++) fma2(acc[i][p], ad[i], wv[p]);
    }
    __syncthreads();

    // pre[128][130] reuses smem
    float* pre = sm;
    #pragma unroll
    for (int i = 0; i < 8; i++)
        #pragma unroll
        for (int p = 0; p < 4; p++)
            *reinterpret_cast<float2*>(pre + (rg + 16 * i) * 130 + 8 * cg + 2 * p) =
                *reinterpret_cast<float2*>(&acc[i][p]);
    __syncthreads();

    // Pool(4,s2,p1)+relu+stats. thread = (row = t&127, half) -> 4 oj groups
    const int row = t & 127, half = t >> 7;
    const float* pr = pre + row * 130;
    long base = (long)(b0 + row) * 1152;
    #pragma unroll
    for (int gg = 0; gg < 4; gg++) {
        int g = half * 4 + gg;
        int oj = oj0 + g;
        int o = oj / 9, jj = oj - o * 9;
        float* dst = g_t1 + base + o * 72 + jj * 8;
        float s = 0.f, ss = 0.f;
        float m8[8];
        #pragma unroll
        for (int k = 0; k < 8; k++) {
            int lo = (2 * k - 1 < 0) ? 0 : 2 * k - 1;
            int hi = (2 * k + 2 > 15) ? 15 : 2 * k + 2;
            float m = pr[g * 16 + lo];
            for (int nn = lo + 1; nn <= hi; nn++) m = fmaxf(m, pr[g * 16 + nn]);
            m = fmaxf(m, 0.f);
            m8[k] = m;
            s += m; ss += m * m;
        }
        *reinterpret_cast<float4*>(dst)     = make_float4(m8[0], m8[1], m8[2], m8[3]);
        *reinterpret_cast<float4*>(dst + 4) = make_float4(m8[4], m8[5], m8[6], m8[7]);
        float sA = warp_sum(s), ssA = warp_sum(ss);
        if ((t & 31) == 0) {
            atomicAdd(&g_red[o], sA);
            atomicAdd(&g_red[16 + o], ssA);
        }
    }
}

__global__ void k_bnparam(const float* __restrict__ g, const float* __restrict__ b, int layer) {
    int c = threadIdx.x;
    int nch, off; float count; float* bn;
    if (layer == 1)      { nch = 16; off = 0;  count = 294912.f; bn = g_bn1; }
    else if (layer == 2) { nch = 32; off = 32; count = 114688.f; bn = g_bn2; }
    else                 { nch = 64; off = 96; count = 20480.f;  bn = g_bn3; }
    if (c >= nch) return;
    float sum = g_red[off + c], ssq = g_red[off + nch + c];
    float mean = sum / count;
    float var = ssq / count - mean * mean;
    float sc = g[c] * rsqrtf(var + 2e-5f);
    bn[c] = sc;
    bn[nch + c] = b[c] - mean * sc;
}

// ---------------------------------------------------------------------------
// Layer2: per j: C[4096 x 256] = acts[4096 x 384] * A2[j], BN1 folded,
// fused pool+relu+stats. Block 128 rows x 128 cols (16 o2), 256 threads,
// col-pair FMA2 scalar-a scheme. K in 6 tiles of 64. 2 blk/SM.
// smem: aT[64][129] + wT[64][130] = 66304 B; pre needs 66560 -> dyn 66560.
// ---------------------------------------------------------------------------
__global__ void __launch_bounds__(256, 2) k_layer2() {
    extern __shared__ float sm[];
    __shared__ float bnS[32];
    float* aT = sm;               // [64][129]
    float* wT = sm + 8256;        // [64][130]
    const int t = threadIdx.x;
    const int b0 = blockIdx.x * 128;
    const int cb = blockIdx.y;    // col block: o2 channels cb*16..+15
    const int j  = blockIdx.z;
    const int rg = t & 15, cg = t >> 4;

    if (t < 32) bnS[t] = g_bn1[t];

    ull acc[8][4];
    #pragma unroll
    for (int i = 0; i < 8; i++)
        #pragma unroll
        for (int p = 0; p < 4; p++) acc[i][p] = 0ull;

    const float* wbase = g_A2 + j * 98304 + cb * 128;

    for (int kt = 0; kt < 6; kt++) {
        __syncthreads();
        // acts tile transposed (BN1 folded): aT[kk][r]
        for (int i = t; i < 8192; i += 256) {
            int r = i >> 6, kk = i & 63;
            int k = kt * 64 + kk;
            int c = k / 24, rem = k - c * 24;
            float v = g_t1[(long)(b0 + r) * 1152 + c * 72 + j * 8 + rem];
            aT[kk * 129 + r] = v * bnS[c] + bnS[16 + c];
        }
        // weight tile natural: wT[kk][col], col < 128
        for (int i = t; i < 8192; i += 256) {
            int kk = i >> 7, col = i & 127;
            wT[kk * 130 + col] = wbase[(kt * 64 + kk) * 256 + col];
        }
        __syncthreads();

        const float* pa = aT + rg;
        const float* pw = wT + 8 * cg;
        #pragma unroll 2
        for (int k = 0; k < 64; k++) {
            ull wv[4];
            #pragma unroll
            for (int p = 0; p < 4; p++)
                wv[p] = *reinterpret_cast<const ull*>(pw + k * 130 + 2 * p);
            ull ad[8];
            #pragma unroll
            for (int i = 0; i < 8; i++) ad[i] = dup2(pa[k * 129 + 16 * i]);
            #pragma unroll
            for (int i = 0; i < 8; i++)
                #pragma unroll
                for (int p = 0; p < 4; p++) fma2(acc[i][p], ad[i], wv[p]);
        }
    }
    __syncthreads();

    float* pre = sm;              // [128][130]
    #pragma unroll
    for (int i = 0; i < 8; i++)
        #pragma unroll
        for (int p = 0; p < 4; p++)
            *reinterpret_cast<float2*>(pre + (rg + 16 * i) * 130 + 8 * cg + 2 * p) =
                *reinterpret_cast<float2*>(&acc[i][p]);
    __syncthreads();

    // Pool(4,s2,p1)+relu+stats. thread = (row, half) -> 8 o2 channels
    const int row = t & 127, half = t >> 7;
    const float* pr = pre + row * 130;
    long tbase = (long)(b0 + row) * 896 + j * 4;
    #pragma unroll
    for (int ol = 0; ol < 8; ol++) {
        int lc = half * 8 + ol;             // local o2 within block (0..15)
        int o2g = cb * 16 + lc;             // global o2 channel
        float s = 0.f, ss = 0.f;
        float m4[4];
        #pragma unroll
        for (int k = 0; k < 4; k++) {
            int lo = (2 * k - 1 < 0) ? 0 : 2 * k - 1;
            int hi = (2 * k + 2 > 7) ? 7 : 2 * k + 2;
            float m = pr[lc * 8 + lo];
            for (int nn = lo + 1; nn <= hi; nn++) m = fmaxf(m, pr[lc * 8 + nn]);
            m = fmaxf(m, 0.f);
            m4[k] = m;
            s += m; ss += m * m;
        }
        *reinterpret_cast<float4*>(g_t2 + tbase + o2g * 28) =
            make_float4(m4[0], m4[1], m4[2], m4[3]);
        float sA = warp_sum(s), ssA = warp_sum(ss);
        if ((t & 31) == 0) {
            atomicAdd(&g_red[32 + o2g], sA);
            atomicAdd(&g_red[64 + o2g], ssA);
        }
    }
}

// ---------------------------------------------------------------------------
// Layer3: per batch-tile of 16 rows. acts transposed [idx 896][18] (BN2 folded)
// so row-pairs are natural LDS.64 (warp-uniform broadcast). Weights [kidx][o3].
// Row-pair f32x2 accumulation halves fma-pipe time vs scalar.
// smem floats: actsT 896*18=16128 | ws 96*64=6144 => 89088 B. 2 blocks/SM.
// ---------------------------------------------------------------------------
__global__ void __launch_bounds__(256, 2) k_layer3(const float* __restrict__ w3) {
    extern __shared__ float sm[];
    float* actsT = sm;             // [896][18]
    float* ws    = sm + 16128;     // [96][64]
    __shared__ float st[128];
    const int t = threadIdx.x;
    const int b0 = blockIdx.x * 16;

    for (int i = t; i < 14336; i += 256) {
        int r = i / 896, idx = i - r * 896;
        int c = idx / 28;
        actsT[idx * 18 + r] = g_t2[(long)b0 * 896 + i] * g_bn2[c] + g_bn2[32 + c];
    }
    for (int i = t; i < 6144; i += 256) {
        int kidx = i >> 6, o = i & 63;
        int c = kidx / 3, rr = kidx - c * 3;
        ws[i] = w3[(o * 32 + c) * 3 + rr];  // w3[...,0]: last dim is 1
    }
    if (t < 128) st[t] = 0.f;
    __syncthreads();

    const int o3 = t & 63, rpg = t >> 6;   // rpg warp-uniform
    const ull* a64 = reinterpret_cast<const ull*>(actsT);  // stride 9 per idx
    const float invj[5] = {1.f, 0.5f, 0.25f, 0.125f, 0.0625f};
    float s = 0.f, ssq = 0.f;

    #pragma unroll
    for (int hf = 0; hf < 2; hf++) {
        const int rp = rpg + 4 * hf;       // row-pair: rows 2rp, 2rp+1
        ull accp[15];
        #pragma unroll
        for (int i = 0; i < 15; i++) accp[i] = 0ull;

        for (int c = 0; c < 32; c++) {
            ull av[21];                    // [m 0..6][l 0..2] row-pairs (broadcast)
            #pragma unroll
            for (int m = 0; m < 7; m++)
                #pragma unroll
                for (int l = 0; l < 3; l++)
                    av[m * 3 + l] = a64[(c * 28 + m * 4 + l) * 9 + rp];
            ull w0 = dup2(ws[(c * 3 + 0) * 64 + o3]);
            ull w1 = dup2(ws[(c * 3 + 1) * 64 + o3]);
            ull w2 = dup2(ws[(c * 3 + 2) * 64 + o3]);
            #pragma unroll
            for (int jj = 0; jj < 5; jj++)
                #pragma unroll
                for (int l = 0; l < 3; l++) {
                    fma2(accp[jj * 3 + l], w0, av[(jj + 0) * 3 + l]);
                    fma2(accp[jj * 3 + l], w1, av[(jj + 1) * 3 + l]);
                    fma2(accp[jj * 3 + l], w2, av[(jj + 2) * 3 + l]);
                }
        }
        // pool over l + relu + scale, both rows of the pair
        #pragma unroll
        for (int jj = 0; jj < 5; jj++) {
            float2 v0 = *reinterpret_cast<float2*>(&accp[jj * 3 + 0]);
            float2 v1 = *reinterpret_cast<float2*>(&accp[jj * 3 + 1]);
            float2 v2 = *reinterpret_cast<float2*>(&accp[jj * 3 + 2]);
            float mx = fmaxf(fmaxf(v0.x, v1.x), v2.x) * invj[jj];
            float my = fmaxf(fmaxf(v0.y, v1.y), v2.y) * invj[jj];
            mx = fmaxf(mx, 0.f); my = fmaxf(my, 0.f);
            g_t3[(b0 + 2 * rp) * 320 + o3 * 5 + jj]     = mx;
            g_t3[(b0 + 2 * rp + 1) * 320 + o3 * 5 + jj] = my;
            s += mx + my; ssq += mx * mx + my * my;
        }
    }
    atomicAdd(&st[o3], s);
    atomicAdd(&st[64 + o3], ssq);
    __syncthreads();
    if (t < 64) { atomicAdd(&g_red[96 + t], st[t]); atomicAdd(&g_red[160 + t], st[64 + t]); }
}

// BN3 + 3-layer MLP. One thread per sample; t3 tiles staged through smem.
__global__ void __launch_bounds__(128) k_fc(const float* __restrict__ fw1, const float* __restrict__ fb1,
                                            const float* __restrict__ fw2, const float* __restrict__ fb2,
                                            const float* __restrict__ fw3, const float* __restrict__ fb3,
                                            float* __restrict__ out) {
    __shared__ float w1s[5120];            // transposed [k][o]
    __shared__ float vt[128 * 33];
    __shared__ float w2s[256];
    __shared__ float w3s[272];
    __shared__ float b1s[16], b2s[16], b3s[17];
    int t = threadIdx.x;
    int bbase = blockIdx.x * 128;
    for (int i = t; i < 5120; i += 128) { int o = i / 320, k = i % 320; w1s[k * 16 + o] = fw1[i]; }
    for (int i = t; i < 256; i += 128) w2s[i] = fw2[i];
    for (int i = t; i < 272; i += 128) w3s[i] = fw3[i];
    if (t < 16) { b1s[t] = fb1[t]; b2s[t] = fb2[t]; }
    if (t < 17) b3s[t] = fb3[t];
    __syncthreads();

    float h1[16];
    #pragma unroll
    for (int o = 0; o < 16; o++) h1[o] = b1s[o];

    for (int i0 = 0; i0 < 320; i0 += 32) {
        __syncthreads();
        for (int idx = t; idx < 4096; idx += 128) {
            int r = idx >> 5, c2 = idx & 31;
            int i = i0 + c2, ch = i / 5;
            vt[r * 33 + c2] = g_t3[(bbase + r) * 320 + i] * g_bn3[ch] + g_bn3[64 + ch];
        }
        __syncthreads();
        #pragma unroll 4
        for (int c2 = 0; c2 < 32; c2++) {
            float v = vt[t * 33 + c2];
            const float* wr = &w1s[(i0 + c2) * 16];
            #pragma unroll
            for (int o = 0; o < 16; o++) h1[o] += v * wr[o];
        }
    }
    float h2[16];
    #pragma unroll
    for (int o = 0; o < 16; o++) {
        float a = b2s[o];
        #pragma unroll
        for (int k = 0; k < 16; k++) a += h1[k] * w2s[o * 16 + k];
        h2[o] = a;
    }
    int b = bbase + t;
    #pragma unroll
    for (int o = 0; o < 17; o++) {
        float a = b3s[o];
        #pragma unroll
        for (int k = 0; k < 16; k++) a += h2[k] * w3s[o * 16 + k];
        out[b * 17 + o] = a;
    }
}

extern "C" void kernel_launch(void* const* d_in, const int* in_sizes, int n_in,
                              void* d_out, int out_size) {
    const float* x   = (const float*)d_in[0];
    const float* w1  = (const float*)d_in[1];
    const float* w2  = (const float*)d_in[2];
    const float* w3  = (const float*)d_in[3];
    const float* g1  = (const float*)d_in[4];
    const float* b1  = (const float*)d_in[5];
    const float* g2  = (const float*)d_in[6];
    const float* b2  = (const float*)d_in[7];
    const float* g3  = (const float*)d_in[8];
    const float* b3  = (const float*)d_in[9];
    const float* fw1 = (const float*)d_in[10];
    const float* fb1 = (const float*)d_in[11];
    const float* fw2 = (const float*)d_in[12];
    const float* fb2 = (const float*)d_in[13];
    const float* fw3 = (const float*)d_in[14];
    const float* fb3 = (const float*)d_in[15];
    float* out = (float*)d_out;

    cudaFuncSetAttribute(k_layer1, cudaFuncAttributeMaxDynamicSharedMemorySize, 99456);
    cudaFuncSetAttribute(k_layer2, cudaFuncAttributeMaxDynamicSharedMemorySize, 66560);
    cudaFuncSetAttribute(k_layer3, cudaFuncAttributeMaxDynamicSharedMemorySize, 89088);

    k_zero<<<1, 256>>>();
    k_prep1<<<(221184 + 255) / 256, 256>>>(w1);
    k_prep2<<<(688128 + 255) / 256, 256>>>(w2);
    k_layer1<<<dim3(32, 18), 256, 99456>>>(x);
    k_bnparam<<<1, 64>>>(g1, b1, 1);
    k_layer2<<<dim3(32, 2, 7), 256, 66560>>>();
    k_bnparam<<<1, 64>>>(g2, b2, 2);
    k_layer3<<<256, 256, 89088>>>(w3);
    k_bnparam<<<1, 64>>>(g3, b3, 3);
    k_fc<<<32, 128>>>(fw1, fb1, fw2, fb2, fw3, fb3, out);
}

// round 10
// speedup vs baseline: 1.4642x; 1.1007x over previous
#include <cuda_runtime.h>

// ---------------- scratch (device globals; no allocation allowed) ----------------
__device__ float g_A1[221184];    // layer1 eff weights, k-major: [kk(96)][ojcol(2304)=oj*16+n]
__device__ float g_A2[688128];    // layer2 eff weights: [j][kk(384)][col(256)] (BN1-scaled in place)
__device__ float g_t1[4718592];   // transposed: [kidx(1152)=c*72+j*8+n][b(4096)]
__device__ float g_t2[3670016];   // transposed: [idx(896)=c*28+j*4+l][b(4096)]
__device__ float g_t3[1310720];   // transposed: [idx(320)=o*5+j][b(4096)]
__device__ float g_red[224];      // sum1[16] ssq1[16] sum2[32] ssq2[32] sum3[64] ssq3[64]
__device__ float g_bn1[32];       // [scale16][shift16]
__device__ float g_bn2[64];       // [scale32][shift32]
__device__ float g_bn3[128];      // [scale64][shift64]
__device__ float g_bias2[1792];   // [j(7)][col(256)]  BN1-shift folded through A2
__device__ float g_w3f[6144];     // [kidx(96)=c*3+rr][o3(64)]  BN2-scale folded
__device__ float g_bias3[64];     // BN2-shift folded through w3
__device__ float g_fw1f[5120];    // transposed [k(320)][o(16)], BN3-scale folded
__device__ float g_fb1f[16];      // BN3-shift folded

typedef unsigned long long ull;

__device__ __forceinline__ void fma2(ull& d, ull a, ull b) {
    asm("fma.rn.f32x2 %0, %1, %2, %0;" : "+l"(d) : "l"(a), "l"(b));
}
__device__ __forceinline__ ull dup2(float v) {
    ull r;
    asm("mov.b64 %0, {%1, %1};" : "=l"(r) : "f"(v));
    return r;
}
__device__ __forceinline__ float warp_sum(float v) {
    #pragma unroll
    for (int o = 16; o; o >>= 1) v += __shfl_down_sync(0xffffffffu, v, o);
    return v;
}

__global__ void k_zero() {
    if (threadIdx.x < 224) g_red[threadIdx.x] = 0.f;
}

// Build layer1 effective weights, k-major: g_A1[kk*2304 + oj*16 + n]
__global__ void k_prep1(const float* __restrict__ w1) {
    int id = blockIdx.x * blockDim.x + threadIdx.x;
    if (id >= 221184) return;
    int n  = id & 15;
    int kk = (id >> 4) % 96;
    int oj = id / 1536;
    int o = oj / 9, j = oj % 9;
    int c = kk >> 4, p = kk & 15;
    int h = 1 << j;
    int d = p - n;
    float v = 0.f;
    if (d >= -3 * h && d <= 3 * h) {
        float t = (float)d / (float)h;
        #pragma unroll
        for (int mm = 0; mm < 7; mm++) {
            float hat = 1.f - fabsf(t - (float)(mm - 3));
            if (hat > 0.f) v += w1[(o * 6 + c) * 7 + mm] * hat;
        }
        v /= (float)h;
    }
    g_A1[kk * 2304 + oj * 16 + n] = v;
}

// Build layer2 effective weights. A2[j][kk=(c*3+r)*8+p][col=o*8+n]
__global__ void k_prep2(const float* __restrict__ w2) {
    int id = blockIdx.x * blockDim.x + threadIdx.x;
    if (id >= 688128) return;
    int col = id & 255;
    int kk  = (id >> 8) % 384;
    int j   = id / 98304;
    int o = col >> 3, n = col & 7;
    int p = kk & 7;
    int cr = kk >> 3;               // c*3+r
    int h = 1 << j;
    int d = p - n;
    float v = 0.f;
    if (d >= -h && d <= h) {
        float t = (float)d / (float)h;
        #pragma unroll
        for (int mm = 0; mm < 3; mm++) {
            float hat = 1.f - fabsf(t - (float)(mm - 1));
            if (hat > 0.f) v += w2[(o * 48 + cr) * 3 + mm] * hat;
        }
        v /= (float)h;
    }
    g_A2[id] = v;
}

// bias2[j][col] = sum_kk sh1[c(kk)] * A2[j][kk][col]   (before scaling A2!)
__global__ void k_bias2() {
    int id = blockIdx.x * blockDim.x + threadIdx.x;
    if (id >= 1792) return;
    int j = id >> 8, col = id & 255;
    const float* base = g_A2 + j * 98304 + col;
    float s = 0.f;
    for (int c = 0; c < 16; c++) {
        float sh = g_bn1[16 + c];
        #pragma unroll 4
        for (int rem = 0; rem < 24; rem++)
            s += sh * base[(c * 24 + rem) * 256];
    }
    g_bias2[id] = s;
}

// A2 *= sc1[c(kk)]  (in place; A2 regenerated by k_prep2 every launch)
__global__ void k_scale2() {
    int id = blockIdx.x * blockDim.x + threadIdx.x;
    if (id >= 688128) return;
    int kk = (id >> 8) % 384;
    g_A2[id] *= g_bn1[kk / 24];
}

// g_w3f[kidx*64+o] = w3[o][c][rr] * sc2[c];  g_bias3[o] = sum w3*sh2
__global__ void k_fold3(const float* __restrict__ w3) {
    int id = blockIdx.x * blockDim.x + threadIdx.x;
    if (id < 6144) {
        int kidx = id >> 6, o = id & 63;
        int c = kidx / 3, rr = kidx - c * 3;
        g_w3f[id] = w3[(o * 32 + c) * 3 + rr] * g_bn2[c];
    }
    if (id < 64) {
        float s = 0.f;
        for (int c = 0; c < 32; c++) {
            float sh = g_bn2[32 + c];
            s += (w3[(id * 32 + c) * 3] + w3[(id * 32 + c) * 3 + 1] + w3[(id * 32 + c) * 3 + 2]) * sh;
        }
        g_bias3[id] = s;
    }
}

// g_fw1f[k*16+o] = fw1[o][k]*sc3[k/5];  g_fb1f[o] = fb1[o] + sum_k fw1*sh3
__global__ void k_foldfc(const float* __restrict__ fw1, const float* __restrict__ fb1) {
    int id = blockIdx.x * blockDim.x + threadIdx.x;
    if (id < 5120) {
        int o = id / 320, k = id - o * 320;
        g_fw1f[k * 16 + o] = fw1[id] * g_bn3[k / 5];
    }
    if (id < 16) {
        float s = fb1[id];
        for (int k = 0; k < 320; k++)
            s += fw1[id * 320 + k] * g_bn3[64 + k / 5];
        g_fb1f[id] = s;
    }
}

// ---------------------------------------------------------------------------
// Layer1: C[4096 x 2304] = X[4096 x 96] * A1[96 x 2304], fused pool+relu+stats.
// Block 128 rows x 128 cols (8 oj groups), 256 threads, col-pair FMA2 (R9).
// smem: aT[96][129]=12384 | wT[96][132]=12672 floats => 100224 B. 2 blk/SM.
// ---------------------------------------------------------------------------
__global__ void __launch_bounds__(256, 2) k_layer1(const float* __restrict__ x) {
    extern __shared__ float sm[];
    float* aT = sm;               // [96][129]
    float* wT = sm + 12384;       // [96][132]
    const int t = threadIdx.x;
    const int b0  = blockIdx.x * 128;
    const int oj0 = blockIdx.y * 8;
    const int rg = t & 15, cg = t >> 4;

    // stage X transposed (scalar: LDG coalesced, STS stride-129 conflict-free)
    for (int i = t; i < 12288; i += 256) {
        int r = i / 96, kk = i - r * 96;
        aT[kk * 129 + r] = x[(b0 + r) * 96 + kk];
    }
    // stage W vectorized (A1 k-major, contiguous 128 floats per kk)
    for (int i = t; i < 3072; i += 256) {
        int kk = i >> 5, c4 = (i & 31) * 4;
        float4 v = *reinterpret_cast<const float4*>(g_A1 + kk * 2304 + oj0 * 16 + c4);
        *reinterpret_cast<float4*>(wT + kk * 132 + c4) = v;
    }
    __syncthreads();

    ull acc[8][4];
    #pragma unroll
    for (int i = 0; i < 8; i++)
        #pragma unroll
        for (int p = 0; p < 4; p++) acc[i][p] = 0ull;

    const float* pa = aT + rg;
    const float* pw = wT + 8 * cg;
    #pragma unroll 2
    for (int k = 0; k < 96; k++) {
        ull wv[4];
        #pragma unroll
        for (int p = 0; p < 4; p++)
            wv[p] = *reinterpret_cast<const ull*>(pw + k * 132 + 2 * p);
        ull ad[8];
        #pragma unroll
        for (int i = 0; i < 8; i++) ad[i] = dup2(pa[k * 129 + 16 * i]);
        #pragma unroll
        for (int i = 0; i < 8; i++)
            #pragma unroll
            for (int p = 0; p < 4; p++) fma2(acc[i][p], ad[i], wv[p]);
    }
    __syncthreads();

    // pre[128][130] reuses smem
    float* pre = sm;
    #pragma unroll
    for (int i = 0; i < 8; i++)
        #pragma unroll
        for (int p = 0; p < 4; p++)
            *reinterpret_cast<float2*>(pre + (rg + 16 * i) * 130 + 8 * cg + 2 * p) =
                *reinterpret_cast<float2*>(&acc[i][p]);
    __syncthreads();

    // Pool(4,s2,p1)+relu+stats. thread = (row, half) -> 4 oj groups. Stores to
    // transposed g_t1[kidx][b] (coalesced across row-threads).
    const int row = t & 127, half = t >> 7;
    const float* pr = pre + row * 130;
    #pragma unroll
    for (int gg = 0; gg < 4; gg++) {
        int g = half * 4 + gg;
        int oj = oj0 + g;
        int o = oj / 9, jj = oj - o * 9;
        float* dst = g_t1 + (long)(o * 72 + jj * 8) * 4096 + b0 + row;
        float s = 0.f, ss = 0.f;
        #pragma unroll
        for (int k = 0; k < 8; k++) {
            int lo = (2 * k - 1 < 0) ? 0 : 2 * k - 1;
            int hi = (2 * k + 2 > 15) ? 15 : 2 * k + 2;
            float m = pr[g * 16 + lo];
            for (int nn = lo + 1; nn <= hi; nn++) m = fmaxf(m, pr[g * 16 + nn]);
            m = fmaxf(m, 0.f);
            dst[k * 4096] = m;
            s += m; ss += m * m;
        }
        float sA = warp_sum(s), ssA = warp_sum(ss);
        if ((t & 31) == 0) {
            atomicAdd(&g_red[o], sA);
            atomicAdd(&g_red[16 + o], ssA);
        }
    }
}

__global__ void k_bnparam(const float* __restrict__ g, const float* __restrict__ b, int layer) {
    int c = threadIdx.x;
    int nch, off; float count; float* bn;
    if (layer == 1)      { nch = 16; off = 0;  count = 294912.f; bn = g_bn1; }
    else if (layer == 2) { nch = 32; off = 32; count = 114688.f; bn = g_bn2; }
    else                 { nch = 64; off = 96; count = 20480.f;  bn = g_bn3; }
    if (c >= nch) return;
    float sum = g_red[off + c], ssq = g_red[off + nch + c];
    float mean = sum / count;
    float var = ssq / count - mean * mean;
    float sc = g[c] * rsqrtf(var + 2e-5f);
    bn[c] = sc;
    bn[nch + c] = b[c] - mean * sc;
}

// ---------------------------------------------------------------------------
// Layer2: per j: C[4096 x 256] = acts[4096 x 384] * A2'[j] + bias2[j],
// fused pool+relu+stats. BN1 pre-folded into A2/bias2 -> staging is pure
// vectorized copy from transposed g_t1. Block 128 rows x 128 cols, 256 thr,
// col-pair FMA2. K in 6 tiles of 64.
// smem: aT[64][132] + wT[64][132] = 16896 floats = 67584 B. 2 blk/SM.
// ---------------------------------------------------------------------------
__global__ void __launch_bounds__(256, 2) k_layer2() {
    extern __shared__ float sm[];
    float* aT = sm;               // [64][132]
    float* wT = sm + 8448;        // [64][132]
    const int t = threadIdx.x;
    const int b0 = blockIdx.x * 128;
    const int cb = blockIdx.y;    // col block: o2 channels cb*16..+15
    const int j  = blockIdx.z;
    const int rg = t & 15, cg = t >> 4;

    ull acc[8][4];
    #pragma unroll
    for (int i = 0; i < 8; i++)
        #pragma unroll
        for (int p = 0; p < 4; p++) acc[i][p] = 0ull;

    const float* wbase = g_A2 + j * 98304 + cb * 128;

    for (int kt = 0; kt < 6; kt++) {
        __syncthreads();
        // acts tile: pure float4 copy from transposed g_t1
        for (int i = t; i < 2048; i += 256) {
            int kk = i >> 5, r4 = (i & 31) * 4;
            int k = kt * 64 + kk;
            int c = k / 24, rem = k - c * 24;
            float4 v = *reinterpret_cast<const float4*>(
                g_t1 + (long)(c * 72 + j * 8 + rem) * 4096 + b0 + r4);
            *reinterpret_cast<float4*>(aT + kk * 132 + r4) = v;
        }
        // weight tile: float4 copy
        for (int i = t; i < 2048; i += 256) {
            int kk = i >> 5, c4 = (i & 31) * 4;
            float4 v = *reinterpret_cast<const float4*>(wbase + (kt * 64 + kk) * 256 + c4);
            *reinterpret_cast<float4*>(wT + kk * 132 + c4) = v;
        }
        __syncthreads();

        const float* pa = aT + rg;
        const float* pw = wT + 8 * cg;
        #pragma unroll 2
        for (int k = 0; k < 64; k++) {
            ull wv[4];
            #pragma unroll
            for (int p = 0; p < 4; p++)
                wv[p] = *reinterpret_cast<const ull*>(pw + k * 132 + 2 * p);
            ull ad[8];
            #pragma unroll
            for (int i = 0; i < 8; i++) ad[i] = dup2(pa[k * 132 + 16 * i]);
            #pragma unroll
            for (int i = 0; i < 8; i++)
                #pragma unroll
                for (int p = 0; p < 4; p++) fma2(acc[i][p], ad[i], wv[p]);
        }
    }
    __syncthreads();

    // add bias2 and spill to pre[128][130]
    float* pre = sm;
    {
        const float* bb = g_bias2 + j * 256 + cb * 128 + 8 * cg;
        float2 bv[4];
        #pragma unroll
        for (int p = 0; p < 4; p++) bv[p] = *reinterpret_cast<const float2*>(bb + 2 * p);
        __syncthreads();
        #pragma unroll
        for (int i = 0; i < 8; i++)
            #pragma unroll
            for (int p = 0; p < 4; p++) {
                float2 v = *reinterpret_cast<float2*>(&acc[i][p]);
                v.x += bv[p].x; v.y += bv[p].y;
                *reinterpret_cast<float2*>(pre + (rg + 16 * i) * 130 + 8 * cg + 2 * p) = v;
            }
    }
    __syncthreads();

    // Pool(4,s2,p1)+relu+stats -> transposed g_t2[idx][b]
    const int row = t & 127, half = t >> 7;
    const float* pr = pre + row * 130;
    #pragma unroll
    for (int ol = 0; ol < 8; ol++) {
        int lc = half * 8 + ol;
        int o2g = cb * 16 + lc;
        float* dst = g_t2 + (long)(o2g * 28 + j * 4) * 4096 + b0 + row;
        float s = 0.f, ss = 0.f;
        #pragma unroll
        for (int k = 0; k < 4; k++) {
            int lo = (2 * k - 1 < 0) ? 0 : 2 * k - 1;
            int hi = (2 * k + 2 > 7) ? 7 : 2 * k + 2;
            float m = pr[lc * 8 + lo];
            for (int nn = lo + 1; nn <= hi; nn++) m = fmaxf(m, pr[lc * 8 + nn]);
            m = fmaxf(m, 0.f);
            dst[k * 4096] = m;
            s += m; ss += m * m;
        }
        float sA = warp_sum(s), ssA = warp_sum(ss);
        if ((t & 31) == 0) {
            atomicAdd(&g_red[32 + o2g], sA);
            atomicAdd(&g_red[64 + o2g], ssA);
        }
    }
}

// ---------------------------------------------------------------------------
// Layer3: per batch-tile of 16 rows. acts = pure float4 copy of transposed
// g_t2 into actsT[idx][20-pad]; weights prefolded g_w3f (BN2 in weights/bias3).
// Row-pair f32x2. smem: actsT 896*20=17920 | ws 6144 => 96256 B. 2 blk/SM.
// ---------------------------------------------------------------------------
__global__ void __launch_bounds__(256, 2) k_layer3() {
    extern __shared__ float sm[];
    float* actsT = sm;             // [896][20]
    float* ws    = sm + 17920;     // [96][64]
    __shared__ float st[128];
    const int t = threadIdx.x;
    const int b0 = blockIdx.x * 16;

    for (int i = t; i < 3584; i += 256) {
        int idx = i >> 2, r4 = (i & 3) * 4;
        float4 v = *reinterpret_cast<const float4*>(g_t2 + (long)idx * 4096 + b0 + r4);
        *reinterpret_cast<float4*>(actsT + idx * 20 + r4) = v;
    }
    for (int i = t; i < 6144; i += 256) ws[i] = g_w3f[i];
    if (t < 128) st[t] = 0.f;
    __syncthreads();

    const int o3 = t & 63, rpg = t >> 6;   // rpg warp-uniform
    const ull* a64 = reinterpret_cast<const ull*>(actsT);  // stride 10 per idx
    const float invj[5] = {1.f, 0.5f, 0.25f, 0.125f, 0.0625f};
    const float bias = g_bias3[o3];
    float s = 0.f, ssq = 0.f;

    #pragma unroll
    for (int hf = 0; hf < 2; hf++) {
        const int rp = rpg + 4 * hf;       // row-pair: rows 2rp, 2rp+1
        ull accp[15];
        #pragma unroll
        for (int i = 0; i < 15; i++) accp[i] = 0ull;

        for (int c = 0; c < 32; c++) {
            ull av[21];
            #pragma unroll
            for (int m = 0; m < 7; m++)
                #pragma unroll
                for (int l = 0; l < 3; l++)
                    av[m * 3 + l] = a64[(c * 28 + m * 4 + l) * 10 + rp];
            ull w0 = dup2(ws[(c * 3 + 0) * 64 + o3]);
            ull w1 = dup2(ws[(c * 3 + 1) * 64 + o3]);
            ull w2 = dup2(ws[(c * 3 + 2) * 64 + o3]);
            #pragma unroll
            for (int jj = 0; jj < 5; jj++)
                #pragma unroll
                for (int l = 0; l < 3; l++) {
                    fma2(accp[jj * 3 + l], w0, av[(jj + 0) * 3 + l]);
                    fma2(accp[jj * 3 + l], w1, av[(jj + 1) * 3 + l]);
                    fma2(accp[jj * 3 + l], w2, av[(jj + 2) * 3 + l]);
                }
        }
        #pragma unroll
        for (int jj = 0; jj < 5; jj++) {
            float2 v0 = *reinterpret_cast<float2*>(&accp[jj * 3 + 0]);
            float2 v1 = *reinterpret_cast<float2*>(&accp[jj * 3 + 1]);
            float2 v2 = *reinterpret_cast<float2*>(&accp[jj * 3 + 2]);
            float mx = (fmaxf(fmaxf(v0.x, v1.x), v2.x) + bias) * invj[jj];
            float my = (fmaxf(fmaxf(v0.y, v1.y), v2.y) + bias) * invj[jj];
            mx = fmaxf(mx, 0.f); my = fmaxf(my, 0.f);
            *reinterpret_cast<float2*>(g_t3 + (long)(o3 * 5 + jj) * 4096 + b0 + 2 * rp) =
                make_float2(mx, my);
            s += mx + my; ssq += mx * mx + my * my;
        }
    }
    atomicAdd(&st[o3], s);
    atomicAdd(&st[64 + o3], ssq);
    __syncthreads();
    if (t < 64) { atomicAdd(&g_red[96 + t], st[t]); atomicAdd(&g_red[160 + t], st[64 + t]); }
}

// 3-layer MLP; BN3 prefolded into g_fw1f/g_fb1f; t3 transposed -> vectorized
// staging into vtT[c2][132-pad].
__global__ void __launch_bounds__(128) k_fc(const float* __restrict__ fw2, const float* __restrict__ fb2,
                                            const float* __restrict__ fw3, const float* __restrict__ fb3,
                                            float* __restrict__ out) {
    __shared__ float w1s[5120];            // [k][o]
    __shared__ float vtT[32 * 132];        // [c2][row]
    __shared__ float w2s[256];
    __shared__ float w3s[272];
    __shared__ float b1s[16], b2s[16], b3s[17];
    int t = threadIdx.x;
    int bbase = blockIdx.x * 128;
    for (int i = t; i < 5120; i += 128) w1s[i] = g_fw1f[i];
    for (int i = t; i < 256; i += 128) w2s[i] = fw2[i];
    for (int i = t; i < 272; i += 128) w3s[i] = fw3[i];
    if (t < 16) { b1s[t] = g_fb1f[t]; b2s[t] = fb2[t]; }
    if (t < 17) b3s[t] = fb3[t];
    __syncthreads();

    float h1[16];
    #pragma unroll
    for (int o = 0; o < 16; o++) h1[o] = b1s[o];

    for (int i0 = 0; i0 < 320; i0 += 32) {
        __syncthreads();
        for (int i = t; i < 1024; i += 128) {
            int c2 = i >> 5, r4 = (i & 31) * 4;
            float4 v = *reinterpret_cast<const float4*>(g_t3 + (long)(i0 + c2) * 4096 + bbase + r4);
            *reinterpret_cast<float4*>(vtT + c2 * 132 + r4) = v;
        }
        __syncthreads();
        #pragma unroll 4
        for (int c2 = 0; c2 < 32; c2++) {
            float v = vtT[c2 * 132 + t];
            const float* wr = &w1s[(i0 + c2) * 16];
            #pragma unroll
            for (int o = 0; o < 16; o++) h1[o] += v * wr[o];
        }
    }
    float h2[16];
    #pragma unroll
    for (int o = 0; o < 16; o++) {
        float a = b2s[o];
        #pragma unroll
        for (int k = 0; k < 16; k++) a += h1[k] * w2s[o * 16 + k];
        h2[o] = a;
    }
    int b = bbase + t;
    #pragma unroll
    for (int o = 0; o < 17; o++) {
        float a = b3s[o];
        #pragma unroll
        for (int k = 0; k < 16; k++) a += h2[k] * w3s[o * 16 + k];
        out[b * 17 + o] = a;
    }
}

extern "C" void kernel_launch(void* const* d_in, const int* in_sizes, int n_in,
                              void* d_out, int out_size) {
    const float* x   = (const float*)d_in[0];
    const float* w1  = (const float*)d_in[1];
    const float* w2  = (const float*)d_in[2];
    const float* w3  = (const float*)d_in[3];
    const float* g1  = (const float*)d_in[4];
    const float* b1  = (const float*)d_in[5];
    const float* g2  = (const float*)d_in[6];
    const float* b2  = (const float*)d_in[7];
    const float* g3  = (const float*)d_in[8];
    const float* b3  = (const float*)d_in[9];
    const float* fw1 = (const float*)d_in[10];
    const float* fb1 = (const float*)d_in[11];
    const float* fw2 = (const float*)d_in[12];
    const float* fb2 = (const float*)d_in[13];
    const float* fw3 = (const float*)d_in[14];
    const float* fb3 = (const float*)d_in[15];
    float* out = (float*)d_out;

    cudaFuncSetAttribute(k_layer1, cudaFuncAttributeMaxDynamicSharedMemorySize, 100224);
    cudaFuncSetAttribute(k_layer2, cudaFuncAttributeMaxDynamicSharedMemorySize, 67584);
    cudaFuncSetAttribute(k_layer3, cudaFuncAttributeMaxDynamicSharedMemorySize, 96256);

    k_zero<<<1, 256>>>();
    k_prep1<<<(221184 + 255) / 256, 256>>>(w1);
    k_prep2<<<(688128 + 255) / 256, 256>>>(w2);
    k_layer1<<<dim3(32, 18), 256, 100224>>>(x);
    k_bnparam<<<1, 64>>>(g1, b1, 1);
    k_bias2<<<7, 256>>>();
    k_scale2<<<2688, 256>>>();
    k_layer2<<<dim3(32, 2, 7), 256, 67584>>>();
    k_bnparam<<<1, 64>>>(g2, b2, 2);
    k_fold3<<<24, 256>>>(w3);
    k_layer3<<<256, 256, 96256>>>();
    k_bnparam<<<1, 64>>>(g3, b3, 3);
    k_foldfc<<<21, 256>>>(fw1, fb1);
    k_fc<<<32, 128>>>(fw2, fb2, fw3, fb3, out);
}